// round 1
// baseline (speedup 1.0000x reference)
#include <cuda_runtime.h>
#include <math.h>

#define NHEADS 16
#define NKVH   8
#define HDIM   64
#define QLEN   2048
#define CTXLEN 2048
#define TOT    4096
#define HID    1024

// Scratch (allocation-free rule: __device__ globals)
static __device__ float g_q [QLEN * NHEADS * HDIM];   // 8 MB
static __device__ float g_k [TOT  * NKVH   * HDIM];   // 8 MB
static __device__ float g_v [TOT  * NKVH   * HDIM];   // 8 MB
static __device__ float g_ao[QLEN * NHEADS * HDIM];   // 8 MB

// ---------------------------------------------------------------------------
// Generic tiled fp32 GEMM: C[M,N] = A[M,K] @ B[K,N].  BM=BN=64, BK=16,
// 256 threads, 4x4 microtile. All problem dims divisible by 64/16.
// ---------------------------------------------------------------------------
__global__ void gemm64(const float* __restrict__ A, const float* __restrict__ B,
                       float* __restrict__ C, int M, int N, int K) {
    __shared__ float As[64][17];   // [m][k], pad 17 kills 2-way bcast conflicts
    __shared__ float Bs[16][64];   // [k][n], float4-aligned
    int bm = blockIdx.y * 64, bn = blockIdx.x * 64;
    int tid = threadIdx.x;
    int tx = tid & 15, ty = tid >> 4;
    float acc[4][4] = {};
    for (int k0 = 0; k0 < K; k0 += 16) {
        #pragma unroll
        for (int p = 0; p < 4; p++) {
            int idx = tid + p * 256;
            int m = idx >> 4, kk = idx & 15;
            As[m][kk] = A[(size_t)(bm + m) * K + k0 + kk];
            int kb = idx >> 6, n = idx & 63;
            Bs[kb][n] = B[(size_t)(k0 + kb) * N + bn + n];
        }
        __syncthreads();
        #pragma unroll
        for (int kk = 0; kk < 16; kk++) {
            float a0 = As[ty*4+0][kk], a1 = As[ty*4+1][kk];
            float a2 = As[ty*4+2][kk], a3 = As[ty*4+3][kk];
            float4 b = *(const float4*)&Bs[kk][tx*4];
            acc[0][0]+=a0*b.x; acc[0][1]+=a0*b.y; acc[0][2]+=a0*b.z; acc[0][3]+=a0*b.w;
            acc[1][0]+=a1*b.x; acc[1][1]+=a1*b.y; acc[1][2]+=a1*b.z; acc[1][3]+=a1*b.w;
            acc[2][0]+=a2*b.x; acc[2][1]+=a2*b.y; acc[2][2]+=a2*b.z; acc[2][3]+=a2*b.w;
            acc[3][0]+=a3*b.x; acc[3][1]+=a3*b.y; acc[3][2]+=a3*b.z; acc[3][3]+=a3*b.w;
        }
        __syncthreads();
    }
    #pragma unroll
    for (int i = 0; i < 4; i++) {
        float4 v = make_float4(acc[i][0], acc[i][1], acc[i][2], acc[i][3]);
        *(float4*)&C[(size_t)(bm + ty*4 + i) * N + bn + tx*4] = v;
    }
}

// ---------------------------------------------------------------------------
// RMS-norm + RoPE, in place on g_q and g_k. One warp per (row, head) vector
// of 64. Lane l holds x[l] and x[l+32] (exactly the rotate_half pairs).
// q at position CTX+row, k at position row.
// ---------------------------------------------------------------------------
__global__ void norm_rope(const float* __restrict__ cosb, const float* __restrict__ sinb,
                          const float* __restrict__ qw,   const float* __restrict__ kw) {
    int warp = (blockIdx.x * blockDim.x + threadIdx.x) >> 5;
    int lane = threadIdx.x & 31;
    float* ptr; int pos; const float* w;
    if (warp < QLEN * NHEADS) {
        int row = warp / NHEADS, h = warp % NHEADS;
        ptr = g_q + (size_t)row * (NHEADS*HDIM) + h * HDIM;
        pos = CTXLEN + row; w = qw;
    } else {
        int v2 = warp - QLEN * NHEADS;
        int row = v2 / NKVH, h = v2 % NKVH;
        ptr = g_k + (size_t)row * (NKVH*HDIM) + h * HDIM;
        pos = row; w = kw;
    }
    float x0 = ptr[lane], x1 = ptr[lane + 32];
    float ss = x0*x0 + x1*x1;
    #pragma unroll
    for (int o = 16; o; o >>= 1) ss += __shfl_xor_sync(0xffffffffu, ss, o);
    float r = rsqrtf(ss * (1.0f/64.0f) + 1e-6f);
    x0 *= r * w[lane];
    x1 *= r * w[lane + 32];
    float c0 = cosb[(size_t)pos*HDIM + lane],      c1 = cosb[(size_t)pos*HDIM + lane + 32];
    float s0 = sinb[(size_t)pos*HDIM + lane],      s1 = sinb[(size_t)pos*HDIM + lane + 32];
    ptr[lane]      = x0 * c0 - x1 * s0;
    ptr[lane + 32] = x1 * c1 + x0 * s1;
}

// ---------------------------------------------------------------------------
// Flash attention with online softmax + block-diagonal tree bias.
// Block = (qtile qb in 0..31, head h in 0..15). 256 threads (16x16),
// 4x4 microtiles for both QK^T and PV. 64x64 tiles, HD=64.
// Dynamic smem: Qs[64][65] | Ks^T[64][68] | Vs[64][68] | Ps[64][65] | stats
// ---------------------------------------------------------------------------
#define ATTN_SMEM_FLOATS (64*65 + 64*68 + 64*68 + 64*65 + 192)
#define ATTN_SMEM_BYTES  (ATTN_SMEM_FLOATS * 4)

__global__ void attn_kernel(const float* __restrict__ mask,
                            const float* __restrict__ tree_bias,
                            const int*   __restrict__ relmap) {
    extern __shared__ float sm[];
    float (*Qs)[65] = (float(*)[65])(sm);
    float (*Ks)[68] = (float(*)[68])(sm + 64*65);              // transposed: [d][kk]
    float (*Vs)[68] = (float(*)[68])(sm + 64*65 + 64*68);      // natural: [kk][d]
    float (*Ps)[65] = (float(*)[65])(sm + 64*65 + 2*64*68);
    float* sm_m  = sm + 2*64*65 + 2*64*68;
    float* sm_l  = sm_m + 64;
    float* sm_sc = sm_l + 64;

    int qb  = blockIdx.x;        // 0..31
    int h   = blockIdx.y;        // 0..15
    int kvh = h >> 1;            // groups = 2
    int tid = threadIdx.x;
    int tx  = tid & 15, ty = tid >> 4;

    for (int i = tid; i < 64*64; i += 256) {
        int ql = i >> 6, d = i & 63;
        Qs[ql][d] = g_q[(size_t)(qb*64 + ql) * (NHEADS*HDIM) + h*HDIM + d];
    }
    if (tid < 64) { sm_m[tid] = -1e30f; sm_l[tid] = 0.0f; }
    float o[4][4] = {};
    __syncthreads();

    for (int kt = 0; kt < 64; kt++) {
        for (int i = tid; i < 64*64; i += 256) {
            int kk = i >> 6, d = i & 63;
            size_t base = (size_t)(kt*64 + kk) * (NKVH*HDIM) + kvh*HDIM + d;
            Ks[d][kk] = g_k[base];
            Vs[kk][d] = g_v[base];
        }
        __syncthreads();

        // S = Q @ K^T
        float s[4][4] = {};
        #pragma unroll 8
        for (int d = 0; d < 64; d++) {
            float a0 = Qs[ty*4+0][d], a1 = Qs[ty*4+1][d];
            float a2 = Qs[ty*4+2][d], a3 = Qs[ty*4+3][d];
            float4 kb = *(const float4*)&Ks[d][tx*4];
            s[0][0]+=a0*kb.x; s[0][1]+=a0*kb.y; s[0][2]+=a0*kb.z; s[0][3]+=a0*kb.w;
            s[1][0]+=a1*kb.x; s[1][1]+=a1*kb.y; s[1][2]+=a1*kb.z; s[1][3]+=a1*kb.w;
            s[2][0]+=a2*kb.x; s[2][1]+=a2*kb.y; s[2][2]+=a2*kb.z; s[2][3]+=a2*kb.w;
            s[3][0]+=a3*kb.x; s[3][1]+=a3*kb.y; s[3][2]+=a3*kb.z; s[3][3]+=a3*kb.w;
        }

        // scale + mask (+ tree bias on the one diagonal noise tile)
        int qg = qb*64 + ty*4;
        int kg = kt*64 + tx*4;
        #pragma unroll
        for (int i = 0; i < 4; i++)
            #pragma unroll
            for (int j = 0; j < 4; j++)
                s[i][j] = s[i][j]*0.125f + mask[(size_t)(qg+i)*TOT + kg + j];
        if (kt == 32 + qb) {
            #pragma unroll
            for (int i = 0; i < 4; i++)
                #pragma unroll
                for (int j = 0; j < 4; j++) {
                    int r = relmap[qb*4096 + (ty*4+i)*64 + (tx*4+j)];
                    s[i][j] += tree_bias[r*NHEADS + h];
                }
        }
        #pragma unroll
        for (int i = 0; i < 4; i++)
            #pragma unroll
            for (int j = 0; j < 4; j++)
                Ps[ty*4+i][tx*4+j] = s[i][j];
        __syncthreads();

        // online softmax update, one thread per query row
        if (tid < 64) {
            float m_old = sm_m[tid];
            float mx = m_old;
            #pragma unroll 8
            for (int kk = 0; kk < 64; kk++) mx = fmaxf(mx, Ps[tid][kk]);
            float sc = __expf(m_old - mx);
            float l  = sm_l[tid] * sc;
            #pragma unroll 8
            for (int kk = 0; kk < 64; kk++) {
                float p = __expf(Ps[tid][kk] - mx);
                Ps[tid][kk] = p;
                l += p;
            }
            sm_m[tid] = mx; sm_l[tid] = l; sm_sc[tid] = sc;
        }
        __syncthreads();

        // rescale O, accumulate O += P @ V
        #pragma unroll
        for (int i = 0; i < 4; i++) {
            float sc = sm_sc[ty*4+i];
            o[i][0]*=sc; o[i][1]*=sc; o[i][2]*=sc; o[i][3]*=sc;
        }
        #pragma unroll 8
        for (int kk = 0; kk < 64; kk++) {
            float p0 = Ps[ty*4+0][kk], p1 = Ps[ty*4+1][kk];
            float p2 = Ps[ty*4+2][kk], p3 = Ps[ty*4+3][kk];
            float4 vv = *(const float4*)&Vs[kk][tx*4];
            o[0][0]+=p0*vv.x; o[0][1]+=p0*vv.y; o[0][2]+=p0*vv.z; o[0][3]+=p0*vv.w;
            o[1][0]+=p1*vv.x; o[1][1]+=p1*vv.y; o[1][2]+=p1*vv.z; o[1][3]+=p1*vv.w;
            o[2][0]+=p2*vv.x; o[2][1]+=p2*vv.y; o[2][2]+=p2*vv.z; o[2][3]+=p2*vv.w;
            o[3][0]+=p3*vv.x; o[3][1]+=p3*vv.y; o[3][2]+=p3*vv.z; o[3][3]+=p3*vv.w;
        }
        __syncthreads();
    }

    #pragma unroll
    for (int i = 0; i < 4; i++) {
        float inv = 1.0f / sm_l[ty*4+i];
        size_t off = (size_t)(qb*64 + ty*4 + i) * (NHEADS*HDIM) + h*HDIM + tx*4;
        float4 v = make_float4(o[i][0]*inv, o[i][1]*inv, o[i][2]*inv, o[i][3]*inv);
        *(float4*)&g_ao[off] = v;
    }
}

// ---------------------------------------------------------------------------
extern "C" void kernel_launch(void* const* d_in, const int* in_sizes, int n_in,
                              void* d_out, int out_size) {
    const float* hidden = (const float*)d_in[0];
    const float* target = (const float*)d_in[1];
    const float* cosb   = (const float*)d_in[2];
    const float* sinb   = (const float*)d_in[3];
    const float* mask   = (const float*)d_in[4];
    const float* Wq     = (const float*)d_in[5];
    const float* Wk     = (const float*)d_in[6];
    const float* Wv     = (const float*)d_in[7];
    const float* Wo     = (const float*)d_in[8];
    const float* qw     = (const float*)d_in[9];
    const float* kw     = (const float*)d_in[10];
    const float* tb     = (const float*)d_in[11];
    const int*   rm     = (const int*)d_in[12];
    float* out = (float*)d_out;

    float *pq, *pk, *pv, *pao;
    cudaGetSymbolAddress((void**)&pq,  g_q);
    cudaGetSymbolAddress((void**)&pk,  g_k);
    cudaGetSymbolAddress((void**)&pv,  g_v);
    cudaGetSymbolAddress((void**)&pao, g_ao);

    // Projections
    gemm64<<<dim3(1024/64, 2048/64), 256>>>(hidden, Wq, pq,               2048, 1024, 1024);
    gemm64<<<dim3( 512/64, 2048/64), 256>>>(target, Wk, pk,               2048,  512, 1024);
    gemm64<<<dim3( 512/64, 2048/64), 256>>>(hidden, Wk, pk + 2048*512,    2048,  512, 1024);
    gemm64<<<dim3( 512/64, 2048/64), 256>>>(target, Wv, pv,               2048,  512, 1024);
    gemm64<<<dim3( 512/64, 2048/64), 256>>>(hidden, Wv, pv + 2048*512,    2048,  512, 1024);

    // RMS norm + RoPE (q: 2048*16 warps, k: 4096*8 warps => 65536 warps)
    norm_rope<<<8192, 256>>>(cosb, sinb, qw, kw);

    // Flash attention with tree bias
    cudaFuncSetAttribute(attn_kernel, cudaFuncAttributeMaxDynamicSharedMemorySize,
                         ATTN_SMEM_BYTES);
    attn_kernel<<<dim3(32, 16), 256, ATTN_SMEM_BYTES>>>(mask, tb, rm);

    // Output projection
    gemm64<<<dim3(1024/64, 2048/64), 256>>>(pao, Wo, out, 2048, 1024, 1024);
}

// round 3
// speedup vs baseline: 2.5947x; 2.5947x over previous
#include <cuda_runtime.h>
#include <cuda_bf16.h>
#include <math.h>
#include <stdint.h>

#define NHEADS 16
#define NKVH   8
#define HDIM   64
#define QLEN   2048
#define CTXLEN 2048
#define TOT    4096
#define HID    1024

// fp32 intermediates
static __device__ float g_q [QLEN * NHEADS * HDIM];
static __device__ float g_k [TOT  * NKVH   * HDIM];
static __device__ float g_v [TOT  * NKVH   * HDIM];

// bf16 hi/lo split buffers
static __device__ __nv_bfloat16 c_hid_h[QLEN*HID], c_hid_l[QLEN*HID];
static __device__ __nv_bfloat16 c_tgt_h[CTXLEN*HID], c_tgt_l[CTXLEN*HID];
static __device__ __nv_bfloat16 c_wq_h [HID*1024], c_wq_l [HID*1024];
static __device__ __nv_bfloat16 c_wk_h [HID*512],  c_wk_l [HID*512];
static __device__ __nv_bfloat16 c_wv_h [HID*512],  c_wv_l [HID*512];
static __device__ __nv_bfloat16 c_wo_h [1024*HID], c_wo_l [1024*HID];
static __device__ __nv_bfloat16 c_q_h  [QLEN*1024], c_q_l [QLEN*1024];
static __device__ __nv_bfloat16 c_k_h  [TOT*512],   c_k_l [TOT*512];
static __device__ __nv_bfloat16 c_v_h  [TOT*512],   c_v_l [TOT*512];
static __device__ __nv_bfloat16 c_ao_h [QLEN*1024], c_ao_l[QLEN*1024];

// ---------------- helpers ----------------
__device__ __forceinline__ uint32_t s2u(const void* p) {
    return (uint32_t)__cvta_generic_to_shared(p);
}
#define LDM_X4(r0,r1,r2,r3,a) \
    asm volatile("ldmatrix.sync.aligned.m8n8.x4.shared.b16 {%0,%1,%2,%3},[%4];" \
                 : "=r"(r0),"=r"(r1),"=r"(r2),"=r"(r3) : "r"(a))
#define LDM_X4T(r0,r1,r2,r3,a) \
    asm volatile("ldmatrix.sync.aligned.m8n8.x4.trans.shared.b16 {%0,%1,%2,%3},[%4];" \
                 : "=r"(r0),"=r"(r1),"=r"(r2),"=r"(r3) : "r"(a))
#define MMA_BF16(c,a,b) \
    asm volatile("mma.sync.aligned.m16n8k16.row.col.f32.bf16.bf16.f32 " \
                 "{%0,%1,%2,%3},{%4,%5,%6,%7},{%8,%9},{%0,%1,%2,%3};" \
                 : "+f"(c[0]),"+f"(c[1]),"+f"(c[2]),"+f"(c[3]) \
                 : "r"(a[0]),"r"(a[1]),"r"(a[2]),"r"(a[3]),"r"(b[0]),"r"(b[1]))
#define CP16(dst,src) \
    asm volatile("cp.async.cg.shared.global [%0],[%1],16;" :: "r"(dst),"l"(src))
#define CP_COMMIT() asm volatile("cp.async.commit_group;")
#define CP_WAIT1()  asm volatile("cp.async.wait_group 1;")
#define CP_WAIT0()  asm volatile("cp.async.wait_group 0;")

__device__ __forceinline__ void split2(float a, float b, uint32_t& hi, uint32_t& lo) {
    __nv_bfloat16 ha = __float2bfloat16_rn(a), hb = __float2bfloat16_rn(b);
    float ra = a - __bfloat162float(ha), rb = b - __bfloat162float(hb);
    __nv_bfloat16 la = __float2bfloat16_rn(ra), lb = __float2bfloat16_rn(rb);
    hi = (uint32_t)__bfloat16_as_ushort(ha) | ((uint32_t)__bfloat16_as_ushort(hb) << 16);
    lo = (uint32_t)__bfloat16_as_ushort(la) | ((uint32_t)__bfloat16_as_ushort(lb) << 16);
}

// ---------------- fp32 -> hi/lo bf16 converter ----------------
__global__ void cvt_hilo(const float* __restrict__ src,
                         __nv_bfloat16* __restrict__ hi,
                         __nv_bfloat16* __restrict__ lo, int n) {
    int base = (blockIdx.x * blockDim.x + threadIdx.x) * 4;
    if (base >= n) return;
    float4 v = *(const float4*)(src + base);
    uint32_t h0, l0, h1, l1;
    split2(v.x, v.y, h0, l0);
    split2(v.z, v.w, h1, l1);
    uint2 H = make_uint2(h0, h1), L = make_uint2(l0, l1);
    *(uint2*)(hi + base) = H;
    *(uint2*)(lo + base) = L;
}

// ---------------- tensor-core GEMM: C[M,N] = A@B, 128x128x32 tiles ----------------
// 8 warps (2m x 4n), warp 64x32, m16n8k16 bf16, 3-term split. cp.async 2-stage.
#define ASTR 40
#define BSTR 136
#define STAGE_HALFS (128*ASTR + 128*ASTR/2*0 + 0 + 2*128*ASTR/1*0 + 0)  // placeholder
#define STAGEH (2*128*ASTR + 2*32*BSTR)   // hi+lo A, hi+lo B = 10240+8704 = 18944 halfs
#define GEMM_SMEM_BYTES (2 * STAGEH * 2)  // 2 stages * halfs * 2B = 75776

__device__ __forceinline__ void gemm_body(
    const __nv_bfloat16* __restrict__ Ahi, const __nv_bfloat16* __restrict__ Alo,
    const __nv_bfloat16* __restrict__ Bhi, const __nv_bfloat16* __restrict__ Blo,
    float* __restrict__ C, int N, int K, int bm, int bn, __nv_bfloat16* sm)
{
    int tid = threadIdx.x;
    int lane = tid & 31, warp = tid >> 5;
    int wm = warp >> 2, wn = warp & 3;
    int lr = lane >> 2, lc = lane & 3;

    auto AsH = [&](int s) { return sm + s*STAGEH; };
    auto AsL = [&](int s) { return sm + s*STAGEH + 128*ASTR; };
    auto BsH = [&](int s) { return sm + s*STAGEH + 2*128*ASTR; };
    auto BsL = [&](int s) { return sm + s*STAGEH + 2*128*ASTR + 32*BSTR; };

    int arow = tid >> 2, aseg = tid & 3;      // A: 64 rows x 4 segs, 2 passes
    int brow = tid >> 3, bseg = tid & 7;      // B: 32 rows x 8 segs, 2 passes

    auto load_stage = [&](int s, int k0) {
        __nv_bfloat16 *ah = AsH(s), *al = AsL(s), *bh = BsH(s), *bl = BsL(s);
        #pragma unroll
        for (int r = 0; r < 2; r++) {
            int m = arow + r * 64;
            size_t g = (size_t)(bm + m) * K + k0 + aseg * 8;
            CP16(s2u(ah + m*ASTR + aseg*8), Ahi + g);
            CP16(s2u(al + m*ASTR + aseg*8), Alo + g);
        }
        #pragma unroll
        for (int r = 0; r < 2; r++) {
            int seg = bseg + r * 8;
            size_t g = (size_t)(k0 + brow) * N + bn + seg * 8;
            CP16(s2u(bh + brow*BSTR + seg*8), Bhi + g);
            CP16(s2u(bl + brow*BSTR + seg*8), Blo + g);
        }
        CP_COMMIT();
    };

    float acc[4][4][4] = {};
    int T = K / 32;
    load_stage(0, 0);

    for (int t = 0; t < T; t++) {
        if (t + 1 < T) { load_stage((t + 1) & 1, (t + 1) * 32); CP_WAIT1(); }
        else           { CP_WAIT0(); }
        __syncthreads();
        __nv_bfloat16 *ah_ = AsH(t & 1), *al_ = AsL(t & 1);
        __nv_bfloat16 *bh_ = BsH(t & 1), *bl_ = BsL(t & 1);
        #pragma unroll
        for (int ks = 0; ks < 2; ks++) {
            int kb = ks * 16;
            uint32_t ah[4][4], al[4][4], bh[4][2], bl[4][2];
            #pragma unroll
            for (int mf = 0; mf < 4; mf++) {
                int r = wm*64 + mf*16 + (lane & 15);
                int c = kb + (lane >> 4) * 8;
                LDM_X4(ah[mf][0], ah[mf][1], ah[mf][2], ah[mf][3], s2u(ah_ + r*ASTR + c));
                LDM_X4(al[mf][0], al[mf][1], al[mf][2], al[mf][3], s2u(al_ + r*ASTR + c));
            }
            #pragma unroll
            for (int nfp = 0; nfp < 2; nfp++) {
                int r = kb + (lane & 7) + 8 * ((lane >> 3) & 1);
                int c = wn*32 + nfp*16 + (lane >> 4) * 8;
                LDM_X4T(bh[nfp*2][0], bh[nfp*2][1], bh[nfp*2+1][0], bh[nfp*2+1][1],
                        s2u(bh_ + r*BSTR + c));
                LDM_X4T(bl[nfp*2][0], bl[nfp*2][1], bl[nfp*2+1][0], bl[nfp*2+1][1],
                        s2u(bl_ + r*BSTR + c));
            }
            #pragma unroll
            for (int mf = 0; mf < 4; mf++)
                #pragma unroll
                for (int nf = 0; nf < 4; nf++) {
                    MMA_BF16(acc[mf][nf], al[mf], bh[nf]);
                    MMA_BF16(acc[mf][nf], ah[mf], bl[nf]);
                    MMA_BF16(acc[mf][nf], ah[mf], bh[nf]);
                }
        }
        __syncthreads();
    }
    #pragma unroll
    for (int mf = 0; mf < 4; mf++) {
        int r0 = bm + wm*64 + mf*16 + lr;
        #pragma unroll
        for (int nf = 0; nf < 4; nf++) {
            int c0 = bn + wn*32 + nf*8 + 2*lc;
            *(float2*)&C[(size_t)r0 * N + c0]       = make_float2(acc[mf][nf][0], acc[mf][nf][1]);
            *(float2*)&C[(size_t)(r0 + 8) * N + c0] = make_float2(acc[mf][nf][2], acc[mf][nf][3]);
        }
    }
}

__global__ __launch_bounds__(256, 1)
void gemm_bf3(const __nv_bfloat16* Ahi, const __nv_bfloat16* Alo,
              const __nv_bfloat16* Bhi, const __nv_bfloat16* Blo,
              float* C, int N, int K) {
    extern __shared__ __nv_bfloat16 gsm[];
    gemm_body(Ahi, Alo, Bhi, Blo, C, N, K, blockIdx.y * 128, blockIdx.x * 128, gsm);
}

__global__ __launch_bounds__(256, 1)
void kvproj_bf3(float* __restrict__ Kout, float* __restrict__ Vout) {
    extern __shared__ __nv_bfloat16 gsm[];
    int z = blockIdx.z;
    const __nv_bfloat16 *Ah = (z & 1) ? c_hid_h : c_tgt_h;
    const __nv_bfloat16 *Al = (z & 1) ? c_hid_l : c_tgt_l;
    const __nv_bfloat16 *Bh = (z < 2) ? c_wk_h : c_wv_h;
    const __nv_bfloat16 *Bl = (z < 2) ? c_wk_l : c_wv_l;
    float* C = ((z < 2) ? Kout : Vout) + ((z & 1) ? (size_t)QLEN * 512 : 0);
    gemm_body(Ah, Al, Bh, Bl, C, 512, HID, blockIdx.y * 128, blockIdx.x * 128, gsm);
}

// ---------------- RMS-norm + RoPE -> bf16 hi/lo ----------------
__global__ void norm_rope(const float* __restrict__ cosb, const float* __restrict__ sinb,
                          const float* __restrict__ qw,   const float* __restrict__ kw) {
    int warp = (blockIdx.x * blockDim.x + threadIdx.x) >> 5;
    int lane = threadIdx.x & 31;
    const float* src; size_t off; int pos; const float* w; bool isq;
    if (warp < QLEN * NHEADS) {
        int row = warp / NHEADS, h = warp % NHEADS;
        off = (size_t)row * 1024 + h * HDIM;
        src = g_q + off; pos = CTXLEN + row; w = qw; isq = true;
    } else {
        int v2 = warp - QLEN * NHEADS;
        int row = v2 / NKVH, h = v2 % NKVH;
        off = (size_t)row * 512 + h * HDIM;
        src = g_k + off; pos = row; w = kw; isq = false;
    }
    float x0 = src[lane], x1 = src[lane + 32];
    float ss = x0*x0 + x1*x1;
    #pragma unroll
    for (int o = 16; o; o >>= 1) ss += __shfl_xor_sync(0xffffffffu, ss, o);
    float r = rsqrtf(ss * (1.0f/64.0f) + 1e-6f);
    x0 *= r * w[lane];
    x1 *= r * w[lane + 32];
    float c0 = cosb[(size_t)pos*HDIM + lane], c1 = cosb[(size_t)pos*HDIM + lane + 32];
    float s0 = sinb[(size_t)pos*HDIM + lane], s1 = sinb[(size_t)pos*HDIM + lane + 32];
    float y0 = x0 * c0 - x1 * s0;
    float y1 = x1 * c1 + x0 * s1;
    __nv_bfloat16 h0 = __float2bfloat16_rn(y0), h1 = __float2bfloat16_rn(y1);
    __nv_bfloat16 l0 = __float2bfloat16_rn(y0 - __bfloat162float(h0));
    __nv_bfloat16 l1 = __float2bfloat16_rn(y1 - __bfloat162float(h1));
    __nv_bfloat16 *dh = isq ? c_q_h : c_k_h, *dl = isq ? c_q_l : c_k_l;
    dh[off + lane] = h0;  dh[off + lane + 32] = h1;
    dl[off + lane] = l0;  dl[off + lane + 32] = l1;
}

// ---------------- flash attention, bf16 3-term MMA ----------------
#define PADH 72   // halfs per row (144B = 9*16B, ldmatrix conflict-free)
// smem (halfs): Qh Ql Kh Kl Vh Vl Ph Pl each 64*72=4608 -> 36864 halfs (73728B)
// then Ps_f32[64][68] (17408B), stats 3*64 floats (768B)
#define ATTN_SMEM_BYTES (73728 + 17408 + 768)

__global__ __launch_bounds__(256, 1)
void attn_kernel(const float* __restrict__ mask,
                 const float* __restrict__ tree_bias,
                 const int*   __restrict__ relmap) {
    extern __shared__ char asmem[];
    __nv_bfloat16* Qh = (__nv_bfloat16*)asmem;
    __nv_bfloat16* Ql = Qh + 4608;
    __nv_bfloat16* Kh = Qh + 2*4608;
    __nv_bfloat16* Kl = Qh + 3*4608;
    __nv_bfloat16* Vh = Qh + 4*4608;
    __nv_bfloat16* Vl = Qh + 5*4608;
    __nv_bfloat16* Ph = Qh + 6*4608;
    __nv_bfloat16* Pl = Qh + 7*4608;
    float* Psf   = (float*)(asmem + 73728);
    float* sm_m  = (float*)(asmem + 73728 + 17408);
    float* sm_l  = sm_m + 64;
    float* sm_sc = sm_l + 64;

    int qb = blockIdx.x, h = blockIdx.y;
    int kvh = h >> 1;
    int tid = threadIdx.x;
    int lane = tid & 31, warp = tid >> 5;
    int wm = warp >> 2, wn = warp & 3;
    int lr = lane >> 2, lc = lane & 3;

    // load Q tile (hi+lo)
    {
        int row = tid >> 2;
        #pragma unroll
        for (int i = 0; i < 2; i++) {
            int seg = (tid & 3) + 4 * i;
            size_t g = (size_t)(qb*64 + row) * 1024 + h * HDIM + seg * 8;
            *(uint4*)&Qh[row*PADH + seg*8] = *(const uint4*)&c_q_h[g];
            *(uint4*)&Ql[row*PADH + seg*8] = *(const uint4*)&c_q_l[g];
        }
    }
    if (tid < 64) { sm_m[tid] = -1e30f; sm_l[tid] = 0.0f; }
    float oacc[2][2][4] = {};
    __syncthreads();

    for (int kt = 0; kt < 64; kt++) {
        // load K,V tiles (hi+lo)
        #pragma unroll
        for (int i = 0; i < 2; i++) {
            int kk = (tid >> 3) + 32 * i;
            int seg = tid & 7;
            size_t g = (size_t)(kt*64 + kk) * 512 + kvh * HDIM + seg * 8;
            *(uint4*)&Kh[kk*PADH + seg*8] = *(const uint4*)&c_k_h[g];
            *(uint4*)&Kl[kk*PADH + seg*8] = *(const uint4*)&c_k_l[g];
            *(uint4*)&Vh[kk*PADH + seg*8] = *(const uint4*)&c_v_h[g];
            *(uint4*)&Vl[kk*PADH + seg*8] = *(const uint4*)&c_v_l[g];
        }
        __syncthreads();

        // ---- S = Q @ K^T ----
        float sacc[2][2][4] = {};
        #pragma unroll
        for (int ks = 0; ks < 4; ks++) {
            int kb = ks * 16;
            uint32_t ah[2][4], al[2][4], bh[2][2], bl[2][2];
            #pragma unroll
            for (int mf = 0; mf < 2; mf++) {
                int r = wm*32 + mf*16 + (lane & 15);
                int c = kb + (lane >> 4) * 8;
                LDM_X4(ah[mf][0], ah[mf][1], ah[mf][2], ah[mf][3], s2u(Qh + r*PADH + c));
                LDM_X4(al[mf][0], al[mf][1], al[mf][2], al[mf][3], s2u(Ql + r*PADH + c));
            }
            {
                int r = wn*16 + (lane & 7) + 8 * (lane >> 4);
                int c = kb + 8 * ((lane >> 3) & 1);
                LDM_X4(bh[0][0], bh[0][1], bh[1][0], bh[1][1], s2u(Kh + r*PADH + c));
                LDM_X4(bl[0][0], bl[0][1], bl[1][0], bl[1][1], s2u(Kl + r*PADH + c));
            }
            #pragma unroll
            for (int mf = 0; mf < 2; mf++)
                #pragma unroll
                for (int nf = 0; nf < 2; nf++) {
                    MMA_BF16(sacc[mf][nf], al[mf], bh[nf]);
                    MMA_BF16(sacc[mf][nf], ah[mf], bl[nf]);
                    MMA_BF16(sacc[mf][nf], ah[mf], bh[nf]);
                }
        }

        // scale + mask (+ tree bias on diagonal noise tile) -> Psf
        int qg = qb * 64, kg = kt * 64;
        bool diag = (kt == 32 + qb);
        #pragma unroll
        for (int mf = 0; mf < 2; mf++) {
            int r0 = wm*32 + mf*16 + lr;
            #pragma unroll
            for (int nf = 0; nf < 2; nf++) {
                int c0 = wn*16 + nf*8 + 2*lc;
                float2 m0 = *(const float2*)&mask[(size_t)(qg + r0)     * TOT + kg + c0];
                float2 m1 = *(const float2*)&mask[(size_t)(qg + r0 + 8) * TOT + kg + c0];
                float v0 = sacc[mf][nf][0]*0.125f + m0.x;
                float v1 = sacc[mf][nf][1]*0.125f + m0.y;
                float v2 = sacc[mf][nf][2]*0.125f + m1.x;
                float v3 = sacc[mf][nf][3]*0.125f + m1.y;
                if (diag) {
                    v0 += tree_bias[relmap[qb*4096 +  r0     *64 + c0    ] * NHEADS + h];
                    v1 += tree_bias[relmap[qb*4096 +  r0     *64 + c0 + 1] * NHEADS + h];
                    v2 += tree_bias[relmap[qb*4096 + (r0 + 8)*64 + c0    ] * NHEADS + h];
                    v3 += tree_bias[relmap[qb*4096 + (r0 + 8)*64 + c0 + 1] * NHEADS + h];
                }
                Psf[r0*68 + c0] = v0;      Psf[r0*68 + c0 + 1] = v1;
                Psf[(r0+8)*68 + c0] = v2;  Psf[(r0+8)*68 + c0 + 1] = v3;
            }
        }
        __syncthreads();

        // ---- online softmax: 4 threads per row ----
        {
            int row = tid >> 2, quad = tid & 3;
            float m_old = sm_m[row];
            float mx = m_old;
            #pragma unroll
            for (int j = 0; j < 16; j++) mx = fmaxf(mx, Psf[row*68 + quad*16 + j]);
            mx = fmaxf(mx, __shfl_xor_sync(0xffffffffu, mx, 1));
            mx = fmaxf(mx, __shfl_xor_sync(0xffffffffu, mx, 2));
            float l = 0.0f;
            uint32_t* Ph32 = (uint32_t*)(Ph + row*PADH);
            uint32_t* Pl32 = (uint32_t*)(Pl + row*PADH);
            #pragma unroll
            for (int jj = 0; jj < 8; jj++) {
                float p0 = __expf(Psf[row*68 + quad*16 + 2*jj]     - mx);
                float p1 = __expf(Psf[row*68 + quad*16 + 2*jj + 1] - mx);
                l += p0 + p1;
                uint32_t hi, lo;
                split2(p0, p1, hi, lo);
                Ph32[quad*8 + jj] = hi;
                Pl32[quad*8 + jj] = lo;
            }
            l += __shfl_xor_sync(0xffffffffu, l, 1);
            l += __shfl_xor_sync(0xffffffffu, l, 2);
            if (quad == 0) {
                float sc = __expf(m_old - mx);
                sm_sc[row] = sc;
                sm_l[row]  = sm_l[row] * sc + l;
                sm_m[row]  = mx;
            }
        }
        __syncthreads();

        // ---- rescale O, O += P @ V ----
        #pragma unroll
        for (int mf = 0; mf < 2; mf++) {
            int rb = wm*32 + mf*16;
            float sc0 = sm_sc[rb + lr], sc1 = sm_sc[rb + lr + 8];
            #pragma unroll
            for (int nf = 0; nf < 2; nf++) {
                oacc[mf][nf][0] *= sc0; oacc[mf][nf][1] *= sc0;
                oacc[mf][nf][2] *= sc1; oacc[mf][nf][3] *= sc1;
            }
        }
        #pragma unroll
        for (int ks = 0; ks < 4; ks++) {
            int kb = ks * 16;
            uint32_t ah[2][4], al[2][4], bh[2][2], bl[2][2];
            #pragma unroll
            for (int mf = 0; mf < 2; mf++) {
                int r = wm*32 + mf*16 + (lane & 15);
                int c = kb + (lane >> 4) * 8;
                LDM_X4(ah[mf][0], ah[mf][1], ah[mf][2], ah[mf][3], s2u(Ph + r*PADH + c));
                LDM_X4(al[mf][0], al[mf][1], al[mf][2], al[mf][3], s2u(Pl + r*PADH + c));
            }
            {
                int r = kb + (lane & 7) + 8 * ((lane >> 3) & 1);
                int c = wn*16 + (lane >> 4) * 8;
                LDM_X4T(bh[0][0], bh[0][1], bh[1][0], bh[1][1], s2u(Vh + r*PADH + c));
                LDM_X4T(bl[0][0], bl[0][1], bl[1][0], bl[1][1], s2u(Vl + r*PADH + c));
            }
            #pragma unroll
            for (int mf = 0; mf < 2; mf++)
                #pragma unroll
                for (int nf = 0; nf < 2; nf++) {
                    MMA_BF16(oacc[mf][nf], al[mf], bh[nf]);
                    MMA_BF16(oacc[mf][nf], ah[mf], bl[nf]);
                    MMA_BF16(oacc[mf][nf], ah[mf], bh[nf]);
                }
        }
        __syncthreads();
    }

    // epilogue: divide by l, split to bf16 hi/lo for Wo GEMM
    #pragma unroll
    for (int mf = 0; mf < 2; mf++) {
        int r0 = wm*32 + mf*16 + lr;
        float inv0 = 1.0f / sm_l[r0], inv1 = 1.0f / sm_l[r0 + 8];
        #pragma unroll
        for (int nf = 0; nf < 2; nf++) {
            int c0 = wn*16 + nf*8 + 2*lc;
            size_t o0 = (size_t)(qb*64 + r0)     * 1024 + h*HDIM + c0;
            size_t o1 = (size_t)(qb*64 + r0 + 8) * 1024 + h*HDIM + c0;
            uint32_t hi, lo;
            split2(oacc[mf][nf][0]*inv0, oacc[mf][nf][1]*inv0, hi, lo);
            *(uint32_t*)&c_ao_h[o0] = hi;  *(uint32_t*)&c_ao_l[o0] = lo;
            split2(oacc[mf][nf][2]*inv1, oacc[mf][nf][3]*inv1, hi, lo);
            *(uint32_t*)&c_ao_h[o1] = hi;  *(uint32_t*)&c_ao_l[o1] = lo;
        }
    }
}

// ---------------------------------------------------------------------------
extern "C" void kernel_launch(void* const* d_in, const int* in_sizes, int n_in,
                              void* d_out, int out_size) {
    const float* hidden = (const float*)d_in[0];
    const float* target = (const float*)d_in[1];
    const float* cosb   = (const float*)d_in[2];
    const float* sinb   = (const float*)d_in[3];
    const float* mask   = (const float*)d_in[4];
    const float* Wq     = (const float*)d_in[5];
    const float* Wk     = (const float*)d_in[6];
    const float* Wv     = (const float*)d_in[7];
    const float* Wo     = (const float*)d_in[8];
    const float* qw     = (const float*)d_in[9];
    const float* kw     = (const float*)d_in[10];
    const float* tb     = (const float*)d_in[11];
    const int*   rm     = (const int*)d_in[12];
    float* out = (float*)d_out;

    float *pq, *pk, *pv;
    cudaGetSymbolAddress((void**)&pq, g_q);
    cudaGetSymbolAddress((void**)&pk, g_k);
    cudaGetSymbolAddress((void**)&pv, g_v);

    __nv_bfloat16 *hidh,*hidl,*tgth,*tgtl,*wqh,*wql,*wkh,*wkl,*wvh,*wvl,*woh,*wol,*vh,*vl,*aoh,*aol;
    cudaGetSymbolAddress((void**)&hidh, c_hid_h); cudaGetSymbolAddress((void**)&hidl, c_hid_l);
    cudaGetSymbolAddress((void**)&tgth, c_tgt_h); cudaGetSymbolAddress((void**)&tgtl, c_tgt_l);
    cudaGetSymbolAddress((void**)&wqh,  c_wq_h);  cudaGetSymbolAddress((void**)&wql,  c_wq_l);
    cudaGetSymbolAddress((void**)&wkh,  c_wk_h);  cudaGetSymbolAddress((void**)&wkl,  c_wk_l);
    cudaGetSymbolAddress((void**)&wvh,  c_wv_h);  cudaGetSymbolAddress((void**)&wvl,  c_wv_l);
    cudaGetSymbolAddress((void**)&woh,  c_wo_h);  cudaGetSymbolAddress((void**)&wol,  c_wo_l);
    cudaGetSymbolAddress((void**)&vh,   c_v_h);   cudaGetSymbolAddress((void**)&vl,   c_v_l);
    cudaGetSymbolAddress((void**)&aoh,  c_ao_h);  cudaGetSymbolAddress((void**)&aol,  c_ao_l);

    auto cvt = [&](const float* s, __nv_bfloat16* h, __nv_bfloat16* l, int n) {
        cvt_hilo<<<(n/4 + 255)/256, 256>>>(s, h, l, n);
    };
    cvt(hidden, hidh, hidl, QLEN*HID);
    cvt(target, tgth, tgtl, CTXLEN*HID);
    cvt(Wq, wqh, wql, HID*1024);
    cvt(Wk, wkh, wkl, HID*512);
    cvt(Wv, wvh, wvl, HID*512);
    cvt(Wo, woh, wol, 1024*HID);

    cudaFuncSetAttribute(gemm_bf3, cudaFuncAttributeMaxDynamicSharedMemorySize, GEMM_SMEM_BYTES);
    cudaFuncSetAttribute(kvproj_bf3, cudaFuncAttributeMaxDynamicSharedMemorySize, GEMM_SMEM_BYTES);

    // Q projection -> fp32 g_q
    gemm_bf3<<<dim3(1024/128, QLEN/128), 256, GEMM_SMEM_BYTES>>>(hidh, hidl, wqh, wql, pq, 1024, HID);
    // K/V projections -> fp32 g_k, g_v
    kvproj_bf3<<<dim3(512/128, QLEN/128, 4), 256, GEMM_SMEM_BYTES>>>(pk, pv);

    // V -> bf16 hi/lo
    cvt(pv, vh, vl, TOT*512);

    // RMS norm + RoPE: q,k -> bf16 hi/lo
    norm_rope<<<8192, 256>>>(cosb, sinb, qw, kw);

    // flash attention -> c_ao hi/lo
    cudaFuncSetAttribute(attn_kernel, cudaFuncAttributeMaxDynamicSharedMemorySize, ATTN_SMEM_BYTES);
    attn_kernel<<<dim3(32, 16), 256, ATTN_SMEM_BYTES>>>(mask, tb, rm);

    // output projection
    gemm_bf3<<<dim3(1024/128, QLEN/128), 256, GEMM_SMEM_BYTES>>>(aoh, aol, woh, wol, out, 1024, HID);
}